// round 17
// baseline (speedup 1.0000x reference)
#include <cuda_runtime.h>
#include <cuda_fp16.h>
#include <cstdint>
#include <math.h>

// Problem constants
#define B_    2
#define S_    2048
#define DIM_  2048
#define H_    16
#define DH_   128
#define MROWS (B_ * S_)   // 4096

// ---------------------------------------------------------------------------
// Scratch (allocation-free rule: device globals)
// ---------------------------------------------------------------------------
__device__ __half g_x  [MROWS * DIM_];
__device__ __half g_wq [DIM_ * DIM_];
__device__ __half g_wk [DIM_ * DIM_];
__device__ __half g_wv [DIM_ * DIM_];
__device__ __half g_wo [DIM_ * DIM_];
__device__ __half g_q  [MROWS * DIM_];
__device__ __half g_k  [MROWS * DIM_];
__device__ __half g_v  [MROWS * DIM_];
__device__ __half g_ot [MROWS * DIM_];

// ---------------------------------------------------------------------------
// Helpers
// ---------------------------------------------------------------------------
__device__ __forceinline__ uint32_t smem_u32(const void* p) {
    uint32_t a;
    asm("{ .reg .u64 t; cvta.to.shared.u64 t, %1; cvt.u32.u64 %0, t; }" : "=r"(a) : "l"(p));
    return a;
}
__device__ __forceinline__ void cp_async16(uint32_t dst, const void* src) {
    asm volatile("cp.async.cg.shared.global [%0], [%1], 16;" :: "r"(dst), "l"(src));
}
#define CP_COMMIT() asm volatile("cp.async.commit_group;" ::: "memory")
#define CP_WAIT(n)  asm volatile("cp.async.wait_group %0;" :: "n"(n) : "memory")

__device__ __forceinline__ void ldmatrix_x4(uint32_t& r0, uint32_t& r1,
                                            uint32_t& r2, uint32_t& r3, uint32_t addr) {
    asm volatile("ldmatrix.sync.aligned.m8n8.x4.shared.b16 {%0,%1,%2,%3}, [%4];"
                 : "=r"(r0), "=r"(r1), "=r"(r2), "=r"(r3) : "r"(addr));
}
__device__ __forceinline__ void ldmatrix_x4_trans(uint32_t& r0, uint32_t& r1,
                                                  uint32_t& r2, uint32_t& r3, uint32_t addr) {
    asm volatile("ldmatrix.sync.aligned.m8n8.x4.trans.shared.b16 {%0,%1,%2,%3}, [%4];"
                 : "=r"(r0), "=r"(r1), "=r"(r2), "=r"(r3) : "r"(addr));
}
__device__ __forceinline__ void mma_f16(float* c, const uint32_t* a, const uint32_t* b) {
    asm volatile(
        "mma.sync.aligned.m16n8k16.row.col.f32.f16.f16.f32 "
        "{%0,%1,%2,%3}, {%4,%5,%6,%7}, {%8,%9}, {%0,%1,%2,%3};"
        : "+f"(c[0]), "+f"(c[1]), "+f"(c[2]), "+f"(c[3])
        : "r"(a[0]), "r"(a[1]), "r"(a[2]), "r"(a[3]), "r"(b[0]), "r"(b[1]));
}

// Fast exp2 (degree-5 poly on FMA pipe, avoids MUFU bottleneck)
__device__ __forceinline__ float fexp2(float x) {
    x = fmaxf(x, -80.f);
    float f = x + 12582912.f;
    int  n  = __float_as_int(f) - 0x4B400000;
    float r = x - (f - 12582912.f);
    float p =            1.3333558146e-3f;
    p = fmaf(p, r, 9.6181291076e-3f);
    p = fmaf(p, r, 5.5504108665e-2f);
    p = fmaf(p, r, 2.4022650696e-1f);
    p = fmaf(p, r, 6.9314718056e-1f);
    p = fmaf(p, r, 1.0f);
    return __int_as_float(__float_as_int(p) + (n << 23));
}

__device__ __forceinline__ uint32_t pack_h(float x, float y) {
    __half2 h = __float22half2_rn(make_float2(x, y));
    return *(uint32_t*)&h;
}

// copy 16 bytes smem->reg->gmem with only 4B-aligned smem reads
__device__ __forceinline__ void copy16(const __half* src, __half* dst) {
    uint4 v;
    v.x = *(const uint32_t*)(src + 0);
    v.y = *(const uint32_t*)(src + 2);
    v.z = *(const uint32_t*)(src + 4);
    v.w = *(const uint32_t*)(src + 6);
    *(uint4*)dst = v;
}

// ---------------------------------------------------------------------------
// Convert x + 4 weights to fp16 in one grid (blockIdx.y: 0..3 weights, 4..5 x)
// ---------------------------------------------------------------------------
__global__ void conv_all_kernel(const float* __restrict__ x,
                                const float* __restrict__ w0, const float* __restrict__ w1,
                                const float* __restrict__ w2, const float* __restrict__ w3,
                                __half* __restrict__ xh,
                                __half* __restrict__ h0, __half* __restrict__ h1,
                                __half* __restrict__ h2, __half* __restrict__ h3, int n4)
{
    int i = blockIdx.x * blockDim.x + threadIdx.x;
    if (i >= n4) return;
    const float* in; __half* out;
    switch (blockIdx.y) {
        case 0: in = w0; out = h0; break;
        case 1: in = w1; out = h1; break;
        case 2: in = w2; out = h2; break;
        case 3: in = w3; out = h3; break;
        case 4: in = x;            out = xh;            break;
        default: in = x + 4 * (size_t)n4; out = xh + 4 * (size_t)n4; break;
    }
    float4 v = ((const float4*)in)[i];
    ((uint32_t*)out)[2 * i]     = pack_h(v.x, v.y);
    ((uint32_t*)out)[2 * i + 1] = pack_h(v.z, v.w);
}

// ---------------------------------------------------------------------------
// GEMM core: 2-stage, 2 syncs/iter, BK=64, single pass fp16, fp32 accum.
// Stage = A(16KB) + B(16KB); 2 stages = 64KB dynamic smem, 2 CTAs/SM.
// Block 128x128, 256 threads (8 warps = 4M x 2N).
// ---------------------------------------------------------------------------
#define GBM 128
#define GBN 128
#define GBK 64
#define GSTAGE 32768
#define GEMM_SMEM (2 * GSTAGE)
__device__ __forceinline__ uint32_t swg(int r, int c) {
    return (uint32_t)(r * 128 + ((c ^ (r & 7)) << 4));
}

__device__ __forceinline__ void gemm_core(
    const __half* __restrict__ As, const __half* __restrict__ Bs,
    int bm, int bn, int K, char* sm, float acc[2][8][4])
{
    const int tid  = threadIdx.x;
    const int wid  = tid >> 5;
    const int lane = tid & 31;
    const int mbase = (wid & 3) * 32;
    const int nbase = (wid >> 2) * 64;

    const uint32_t sBase = smem_u32(sm);
    const int NIT = K / GBK;          // 32

    auto issue = [&](int it, int buf) {
        const uint32_t st = sBase + (uint32_t)buf * GSTAGE;
        const int k0 = it * GBK;
#pragma unroll
        for (int i = 0; i < 4; i++) {
            int id = i * 256 + tid;
            int r = id >> 3, c = id & 7;
            uint32_t off = swg(r, c);
            cp_async16(st + off,         As + (size_t)(bm + r) * K + k0 + c * 8);
            cp_async16(st + 16384 + off, Bs + (size_t)(bn + r) * K + k0 + c * 8);
        }
        CP_COMMIT();
    };

#pragma unroll
    for (int mt = 0; mt < 2; mt++)
#pragma unroll
        for (int nt = 0; nt < 8; nt++)
#pragma unroll
            for (int e = 0; e < 4; e++) acc[mt][nt][e] = 0.f;

    issue(0, 0);

    for (int it = 0; it < NIT; it++) {
        const int buf = it & 1;
        if (it + 1 < NIT) {
            issue(it + 1, buf ^ 1);
            CP_WAIT(1);
        } else {
            CP_WAIT(0);
        }
        __syncthreads();

        const uint32_t sA = sBase + (uint32_t)buf * GSTAGE;
        const uint32_t sB = sA + 16384;

#pragma unroll
        for (int ks = 0; ks < 4; ks++) {
            uint32_t afr[2][4];
#pragma unroll
            for (int mt = 0; mt < 2; mt++) {
                int row   = mbase + mt * 16 + (lane & 15);
                int chunk = ks * 2 + (lane >> 4);
                ldmatrix_x4(afr[mt][0], afr[mt][1], afr[mt][2], afr[mt][3],
                            sA + swg(row, chunk));
            }
            uint32_t bfr[8][2];
#pragma unroll
            for (int nt2 = 0; nt2 < 4; nt2++) {
                int row   = nbase + nt2 * 16 + ((lane >> 4) << 3) + (lane & 7);
                int chunk = ks * 2 + ((lane >> 3) & 1);
                ldmatrix_x4(bfr[nt2 * 2][0], bfr[nt2 * 2][1],
                            bfr[nt2 * 2 + 1][0], bfr[nt2 * 2 + 1][1],
                            sB + swg(row, chunk));
            }
#pragma unroll
            for (int mt = 0; mt < 2; mt++)
#pragma unroll
                for (int nt = 0; nt < 8; nt++)
                    mma_f16(acc[mt][nt], afr[mt], bfr[nt]);
        }
        __syncthreads();
    }
}

// ---------------------------------------------------------------------------
// Fused QKV GEMM: blockIdx.z selects {Wq(rope), Wk(rope), Wv}.
// Epilogue stages the fp16 tile in smem, then writes coalesced 16B chunks.
// ---------------------------------------------------------------------------
#define QS 130   // staging stride in fp16

__global__ __launch_bounds__(256, 2) void qkv_gemm(
    const __half* __restrict__ xh,
    const __half* __restrict__ wq, const __half* __restrict__ wk,
    const __half* __restrict__ wv,
    __half* __restrict__ qq, __half* __restrict__ kk, __half* __restrict__ vv,
    const float* __restrict__ cosb, const float* __restrict__ sinb)
{
    extern __shared__ __align__(1024) char smq[];

    const int tid = threadIdx.x;
    const int bm = blockIdx.y * GBM;
    const int bn = blockIdx.x * GBN;
    const int z  = blockIdx.z;

    const __half* Bs = (z == 0) ? wq : (z == 1) ? wk : wv;
    __half* out = (z == 0) ? qq : (z == 1) ? kk : vv;

    float acc[2][8][4];
    gemm_core(xh, Bs, bm, bn, DIM_, smq, acc);

    const int lane = tid & 31;
    const int wid  = tid >> 5;
    const int mbase = (wid & 3) * 32;
    const int nbase = (wid >> 2) * 64;
    const int erow = lane >> 2;
    const int ecol = (lane & 3) * 2;

    __half* sq = (__half*)smq;
#pragma unroll
    for (int mt = 0; mt < 2; mt++) {
#pragma unroll
        for (int nt = 0; nt < 8; nt++) {
            const int lrow = mbase + mt * 16 + erow;
            const int lcol = nbase + nt * 8 + ecol;
            const int grow = bm + lrow;
            const int gcol = bn + lcol;
            float v0 = acc[mt][nt][0], v1 = acc[mt][nt][1];
            float v2 = acc[mt][nt][2], v3 = acc[mt][nt][3];
            if (z < 2) {   // RoPE for q and k
                const int fi = (gcol & 127) >> 1;
                const int s0 = grow & (S_ - 1);
                const int s1 = (grow + 8) & (S_ - 1);
                float c0 = cosb[s0 * 64 + fi], n0 = sinb[s0 * 64 + fi];
                float c1 = cosb[s1 * 64 + fi], n1 = sinb[s1 * 64 + fi];
                float r0 = v0 * c0 - v1 * n0, i0 = v0 * n0 + v1 * c0;
                float r1 = v2 * c1 - v3 * n1, i1 = v2 * n1 + v3 * c1;
                v0 = r0; v1 = i0; v2 = r1; v3 = i1;
            }
            *(uint32_t*)(sq + lrow * QS + lcol)       = pack_h(v0, v1);
            *(uint32_t*)(sq + (lrow + 8) * QS + lcol) = pack_h(v2, v3);
        }
    }
    __syncthreads();

    {
        const int row  = tid & 127;
        const int half = tid >> 7;
        const __half* src = sq + row * QS + half * 64;
        __half* dst = out + (size_t)(bm + row) * DIM_ + bn + half * 64;
#pragma unroll
        for (int i = 0; i < 8; i++) copy16(src + i * 8, dst + i * 8);
    }
}

// Output projection GEMM (fp32 out)
__global__ __launch_bounds__(256, 2) void out_gemm(
    const __half* __restrict__ As, const __half* __restrict__ Bs,
    float* __restrict__ C)
{
    extern __shared__ __align__(1024) char smo[];
    const int bm = blockIdx.y * GBM;
    const int bn = blockIdx.x * GBN;

    float acc[2][8][4];
    gemm_core(As, Bs, bm, bn, DIM_, smo, acc);

    const int lane = threadIdx.x & 31;
    const int wid  = threadIdx.x >> 5;
    const int mbase = (wid & 3) * 32;
    const int nbase = (wid >> 2) * 64;
    const int erow = lane >> 2;
    const int ecol = (lane & 3) * 2;
#pragma unroll
    for (int mt = 0; mt < 2; mt++) {
#pragma unroll
        for (int nt = 0; nt < 8; nt++) {
            const int grow = bm + mbase + mt * 16 + erow;
            const int gcol = bn + nbase + nt * 8 + ecol;
            float* cp0 = C + (size_t)grow * DIM_ + gcol;
            *(float2*)cp0              = make_float2(acc[mt][nt][0], acc[mt][nt][1]);
            *(float2*)(cp0 + 8 * DIM_) = make_float2(acc[mt][nt][2], acc[mt][nt][3]);
        }
    }
}

// ---------------------------------------------------------------------------
// Flash attention v4: 128 q-rows/CTA, 4 warps x 32 q-rows (2 m-tiles each).
// Halves K/V ldsm duplication (ldsm:mma 0.56 -> 0.31) and K/V global traffic.
// kv tiles of 64, double-buffered. smem: Q 32K + 2 x 32K = 96KB, 2 CTAs/SM.
// ---------------------------------------------------------------------------
#define FL_SMEM 98304
#define SOS 130   // O staging stride in fp16 (128 s + pad)

__device__ __forceinline__ uint32_t fl_off(int r, int c) {
    return (uint32_t)(r * 256 + ((c ^ (r & 7)) << 4));
}

__global__ __launch_bounds__(128, 2) void flash_mma(
    const __half* __restrict__ qq, const __half* __restrict__ kk,
    const __half* __restrict__ vv, __half* __restrict__ ot)
{
    extern __shared__ __align__(1024) char sm8[];
    const uint32_t sQ = smem_u32(sm8);

    const int qb = (int)gridDim.x - 1 - blockIdx.x;   // largest first
    const int h = blockIdx.y, b = blockIdx.z;
    const int qbase = qb * 128;
    const int tid = threadIdx.x, wid = tid >> 5, lane = tid & 31;
    const int mbase = wid * 32;                        // 32 q-rows per warp
    const int colbase = h * DH_;
    const size_t rowg0 = ((size_t)b * S_ + qbase) * DIM_ + colbase;

    // Q tile: 128 rows x 16 chunks
#pragma unroll
    for (int i = 0; i < 16; i++) {
        int idx = i * 128 + tid;
        int r = idx >> 4, c = idx & 15;
        size_t g = rowg0 + (size_t)r * DIM_ + c * 8;
        cp_async16(sQ + fl_off(r, c), qq + g);
    }
    CP_COMMIT();

    const int NT = 2 * qb + 2;   // kv tiles of 64

    auto issueKV = [&](int kb, int st) {
        const uint32_t base = sQ + 32768 + st * 32768;
        const size_t krow0 = ((size_t)b * S_ + kb * 64) * DIM_ + colbase;
#pragma unroll
        for (int i = 0; i < 8; i++) {
            int idx = i * 128 + tid;
            int r = idx >> 4, c = idx & 15;
            uint32_t off = fl_off(r, c);
            size_t g = krow0 + (size_t)r * DIM_ + c * 8;
            cp_async16(base + off,         kk + g);
            cp_async16(base + 16384 + off, vv + g);
        }
        CP_COMMIT();
    };

    issueKV(0, 0);

    float m[4] = {-1e30f, -1e30f, -1e30f, -1e30f};
    float l[4] = {0.f, 0.f, 0.f, 0.f};
    float o[2][16][4];
#pragma unroll
    for (int mt = 0; mt < 2; mt++)
#pragma unroll
        for (int nt = 0; nt < 16; nt++)
#pragma unroll
            for (int e = 0; e < 4; e++) o[mt][nt][e] = 0.f;

    const int rA = lane >> 2;
    const int cq = (lane & 3) * 2;
    const float KARG = 0.1275166782f;   // (1/sqrt(128)) * log2(e)

    const int a_r  = (lane & 7) + ((lane >> 3) & 1) * 8;
    const int a_cb = lane >> 4;
    const int bk_r = (lane & 7);
    const int bk_np = lane >> 4;
    const int bk_cb = (lane >> 3) & 1;

    for (int kb = 0; kb < NT; kb++) {
        const int st = kb & 1;
        const uint32_t sK = sQ + 32768 + st * 32768;
        const uint32_t sV = sK + 16384;

        __syncthreads();
        if (kb + 1 < NT) {
            issueKV(kb + 1, st ^ 1);
            CP_WAIT(1);
        } else {
            CP_WAIT(0);
        }
        __syncthreads();

        const bool active = (kb * 64) <= (qbase + mbase + 31);
        if (active) {
            // ---- S = Q @ K^T : 32x64 per warp (2 m-tiles share bk) ----
            float sacc[2][8][4];
#pragma unroll
            for (int mt = 0; mt < 2; mt++)
#pragma unroll
                for (int nt = 0; nt < 8; nt++)
#pragma unroll
                    for (int e = 0; e < 4; e++) sacc[mt][nt][e] = 0.f;

#pragma unroll
            for (int kkk = 0; kkk < 8; kkk++) {
                uint32_t aq[2][4], bk[8][2];
                int achk = 2 * kkk + a_cb;
#pragma unroll
                for (int mt = 0; mt < 2; mt++)
                    ldmatrix_x4(aq[mt][0], aq[mt][1], aq[mt][2], aq[mt][3],
                                sQ + fl_off(mbase + mt * 16 + a_r, achk));
#pragma unroll
                for (int np = 0; np < 4; np++) {
                    int brow = (2 * np + bk_np) * 8 + bk_r;
                    int bchk = 2 * kkk + bk_cb;
                    ldmatrix_x4(bk[2 * np][0], bk[2 * np][1],
                                bk[2 * np + 1][0], bk[2 * np + 1][1],
                                sK + fl_off(brow, bchk));
                }
#pragma unroll
                for (int mt = 0; mt < 2; mt++)
#pragma unroll
                    for (int nt = 0; nt < 8; nt++)
                        mma_f16(sacc[mt][nt], aq[mt], bk[nt]);
            }

            // ---- causal mask + online softmax per m-tile ----
#pragma unroll
            for (int mt = 0; mt < 2; mt++) {
                const int rowbase = qbase + mbase + mt * 16;
                if (kb * 64 + 63 > rowbase) {
                    int rowA = rowbase + rA, rowB = rowA + 8;
#pragma unroll
                    for (int nt = 0; nt < 8; nt++) {
                        int c0 = kb * 64 + nt * 8 + cq;
                        if (c0     > rowA) sacc[mt][nt][0] = -1e30f;
                        if (c0 + 1 > rowA) sacc[mt][nt][1] = -1e30f;
                        if (c0     > rowB) sacc[mt][nt][2] = -1e30f;
                        if (c0 + 1 > rowB) sacc[mt][nt][3] = -1e30f;
                    }
                }

                float tmA = -1e30f, tmB = -1e30f;
#pragma unroll
                for (int nt = 0; nt < 8; nt++) {
                    tmA = fmaxf(tmA, fmaxf(sacc[mt][nt][0], sacc[mt][nt][1]));
                    tmB = fmaxf(tmB, fmaxf(sacc[mt][nt][2], sacc[mt][nt][3]));
                }
                tmA = fmaxf(tmA, __shfl_xor_sync(0xffffffffu, tmA, 1));
                tmA = fmaxf(tmA, __shfl_xor_sync(0xffffffffu, tmA, 2));
                tmB = fmaxf(tmB, __shfl_xor_sync(0xffffffffu, tmB, 1));
                tmB = fmaxf(tmB, __shfl_xor_sync(0xffffffffu, tmB, 2));

                float alpha0 = 1.f, alpha1 = 1.f;
                bool upd0 = (tmA > m[2 * mt]), upd1 = (tmB > m[2 * mt + 1]);
                if (upd0) { alpha0 = fexp2((m[2 * mt]     - tmA) * KARG); m[2 * mt]     = tmA; }
                if (upd1) { alpha1 = fexp2((m[2 * mt + 1] - tmB) * KARG); m[2 * mt + 1] = tmB; }

                float rs0 = 0.f, rs1 = 0.f;
#pragma unroll
                for (int nt = 0; nt < 8; nt++) {
                    float p0 = fexp2((sacc[mt][nt][0] - m[2 * mt])     * KARG);
                    float p1 = fexp2((sacc[mt][nt][1] - m[2 * mt])     * KARG);
                    float p2 = fexp2((sacc[mt][nt][2] - m[2 * mt + 1]) * KARG);
                    float p3 = fexp2((sacc[mt][nt][3] - m[2 * mt + 1]) * KARG);
                    sacc[mt][nt][0] = p0; sacc[mt][nt][1] = p1;
                    sacc[mt][nt][2] = p2; sacc[mt][nt][3] = p3;
                    rs0 += p0 + p1; rs1 += p2 + p3;
                }
                rs0 += __shfl_xor_sync(0xffffffffu, rs0, 1);
                rs0 += __shfl_xor_sync(0xffffffffu, rs0, 2);
                rs1 += __shfl_xor_sync(0xffffffffu, rs1, 1);
                rs1 += __shfl_xor_sync(0xffffffffu, rs1, 2);
                l[2 * mt]     = alpha0 * l[2 * mt]     + rs0;
                l[2 * mt + 1] = alpha1 * l[2 * mt + 1] + rs1;

                if (upd0 || upd1) {
#pragma unroll
                    for (int nt = 0; nt < 16; nt++) {
                        o[mt][nt][0] *= alpha0; o[mt][nt][1] *= alpha0;
                        o[mt][nt][2] *= alpha1; o[mt][nt][3] *= alpha1;
                    }
                }
            }

            // ---- pack P (single fp16), both m-tiles ----
            uint32_t phi[2][4][4];
#pragma unroll
            for (int mt = 0; mt < 2; mt++)
#pragma unroll
                for (int kk2 = 0; kk2 < 4; kk2++) {
                    phi[mt][kk2][0] = pack_h(sacc[mt][2 * kk2][0],     sacc[mt][2 * kk2][1]);
                    phi[mt][kk2][1] = pack_h(sacc[mt][2 * kk2][2],     sacc[mt][2 * kk2][3]);
                    phi[mt][kk2][2] = pack_h(sacc[mt][2 * kk2 + 1][0], sacc[mt][2 * kk2 + 1][1]);
                    phi[mt][kk2][3] = pack_h(sacc[mt][2 * kk2 + 1][2], sacc[mt][2 * kk2 + 1][3]);
                }

            // ---- O += P @ V (bv shared across both m-tiles) ----
#pragma unroll
            for (int kk2 = 0; kk2 < 4; kk2++) {
#pragma unroll
                for (int np = 0; np < 8; np++) {
                    uint32_t bv[4];
                    int vrow = kk2 * 16 + a_r;
                    int vchk = 2 * np + a_cb;
                    ldmatrix_x4_trans(bv[0], bv[1], bv[2], bv[3], sV + fl_off(vrow, vchk));
#pragma unroll
                    for (int mt = 0; mt < 2; mt++) {
                        mma_f16(o[mt][2 * np],     phi[mt][kk2], bv + 0);
                        mma_f16(o[mt][2 * np + 1], phi[mt][kk2], bv + 2);
                    }
                }
            }
        }
    }

    // ---- epilogue: stage O as [col][s] in smem, then coalesced stores ----
    __syncthreads();   // all warps done with K/V smem
    __half* so = (__half*)sm8;
#pragma unroll
    for (int mt = 0; mt < 2; mt++) {
        const float inv0 = 1.f / l[2 * mt], inv1 = 1.f / l[2 * mt + 1];
        const int sloc0 = mbase + mt * 16 + rA;
        const int sloc1 = sloc0 + 8;
#pragma unroll
        for (int nt = 0; nt < 16; nt++) {
            int cl = nt * 8 + cq;
            so[(cl    ) * SOS + sloc0] = __float2half_rn(o[mt][nt][0] * inv0);
            so[(cl + 1) * SOS + sloc0] = __float2half_rn(o[mt][nt][1] * inv0);
            so[(cl    ) * SOS + sloc1] = __float2half_rn(o[mt][nt][2] * inv1);
            so[(cl + 1) * SOS + sloc1] = __float2half_rn(o[mt][nt][3] * inv1);
        }
    }
    __syncthreads();
    // thread tid copies col row tid: 128 fp16 = 256B contiguous in ot
    {
        const __half* src = so + tid * SOS;
        __half* dst = ot + ((size_t)b * DIM_ + colbase + tid) * S_ + qbase;
#pragma unroll
        for (int i = 0; i < 16; i++) copy16(src + i * 8, dst + i * 8);
    }
}

// ---------------------------------------------------------------------------
// Launch
// ---------------------------------------------------------------------------
extern "C" void kernel_launch(void* const* d_in, const int* in_sizes, int n_in,
                              void* d_out, int out_size)
{
    const float* x    = (const float*)d_in[0];
    const float* Wq   = (const float*)d_in[1];
    const float* Wk   = (const float*)d_in[2];
    const float* Wv   = (const float*)d_in[3];
    const float* Wo   = (const float*)d_in[4];
    const float* cosb = (const float*)d_in[5];
    const float* sinb = (const float*)d_in[6];
    // d_in[7] = mask: causal handled analytically

    __half *xh, *wq, *wk, *wv, *wo, *qp, *kp, *vp, *ot;
    cudaGetSymbolAddress((void**)&xh, g_x);
    cudaGetSymbolAddress((void**)&wq, g_wq);
    cudaGetSymbolAddress((void**)&wk, g_wk);
    cudaGetSymbolAddress((void**)&wv, g_wv);
    cudaGetSymbolAddress((void**)&wo, g_wo);
    cudaGetSymbolAddress((void**)&qp, g_q);
    cudaGetSymbolAddress((void**)&kp, g_k);
    cudaGetSymbolAddress((void**)&vp, g_v);
    cudaGetSymbolAddress((void**)&ot, g_ot);

    cudaFuncSetAttribute(flash_mma, cudaFuncAttributeMaxDynamicSharedMemorySize, FL_SMEM);
    cudaFuncSetAttribute(qkv_gemm, cudaFuncAttributeMaxDynamicSharedMemorySize, GEMM_SMEM);
    cudaFuncSetAttribute(out_gemm, cudaFuncAttributeMaxDynamicSharedMemorySize, GEMM_SMEM);

    // Convert x + 4 weights to fp16 (one launch; y=4,5 are x halves)
    {
        int n4w = DIM_ * DIM_ / 4;
        dim3 g(n4w / 256, 6);
        conv_all_kernel<<<g, 256>>>(x, Wq, Wk, Wv, Wo, xh, wq, wk, wv, wo, n4w);
    }

    // Fused QKV projections — one launch, 1-pass each
    dim3 gqkv(DIM_ / GBN, MROWS / GBM, 3);   // (16, 32, 3) = 1536 CTAs
    qkv_gemm<<<gqkv, 256, GEMM_SMEM>>>(xh, wq, wk, wv, qp, kp, vp, cosb, sinb);

    // Tensor-core causal flash attention -> ot transposed (single fp16)
    dim3 gflash(S_ / 128, H_, B_);           // (16, 16, 2) = 512 CTAs
    flash_mma<<<gflash, 128, FL_SMEM>>>(qp, kp, vp, ot);

    // Output projection (fp32 out)
    dim3 ggemm(DIM_ / GBN, MROWS / GBM);     // (16, 32)
    out_gemm<<<ggemm, 256, GEMM_SMEM>>>(ot, wo, (float*)d_out);
}